// round 4
// baseline (speedup 1.0000x reference)
#include <cuda_runtime.h>
#include <cuda_bf16.h>
#include <cstdint>

// ---------------------------------------------------------------------------
// Problem constants
// ---------------------------------------------------------------------------
#define Bsz    2
#define Lseq   1024
#define VOC    32000
#define Dm     512
#define NLAY   2
#define INNER  1024
#define MLPD   2048
#define NSEG   8
#define SEGLEN 128
#define NROWS  (Bsz*Lseq)      // 2048
#define DEC_SK 8
#define DEC_KSLICE (VOC/DEC_SK)   // 4000

// ---------------------------------------------------------------------------
// Scratch (device globals)
// ---------------------------------------------------------------------------
__device__ float g_x      [NROWS * Dm];
__device__ float g_decpart[DEC_SK * NROWS * Dm];
__device__ float g_ug     [NROWS * 2 * INNER];
__device__ float g_h      [NROWS * INNER];
__device__ float g_xs     [NROWS * Dm];
__device__ float g_state  [NLAY * Bsz * NSEG * INNER];
__device__ float g_last   [Bsz * NSEG * Dm];
__device__ int   g_starts [Bsz * NSEG];
__device__ int   g_ends   [Bsz * NSEG];
// bf16 hi/lo operand buffers
__device__ __nv_bfloat16 g_decAh[NROWS * VOC];
__device__ __nv_bfloat16 g_decAl[NROWS * VOC];
__device__ __nv_bfloat16 g_xh   [NROWS * Dm];
__device__ __nv_bfloat16 g_xl   [NROWS * Dm];
__device__ __nv_bfloat16 g_ph   [NROWS * INNER];
__device__ __nv_bfloat16 g_pl   [NROWS * INNER];
__device__ __nv_bfloat16 g_mlph [NROWS * MLPD];
__device__ __nv_bfloat16 g_mlpl [NROWS * MLPD];
__device__ __nv_bfloat16 g_Eh   [VOC * Dm];
__device__ __nv_bfloat16 g_El   [VOC * Dm];
__device__ __nv_bfloat16 g_WinH [NLAY * Dm * 2 * INNER];
__device__ __nv_bfloat16 g_WinL [NLAY * Dm * 2 * INNER];
__device__ __nv_bfloat16 g_WoutH[NLAY * INNER * Dm];
__device__ __nv_bfloat16 g_WoutL[NLAY * INNER * Dm];
__device__ __nv_bfloat16 g_Wm1H [NLAY * Dm * MLPD];
__device__ __nv_bfloat16 g_Wm1L [NLAY * Dm * MLPD];
__device__ __nv_bfloat16 g_Wm2H [NLAY * MLPD * Dm];
__device__ __nv_bfloat16 g_Wm2L [NLAY * MLPD * Dm];

__device__ __forceinline__ float silu_f(float v) { return v * (1.f / (1.f + __expf(-v))); }

__device__ __forceinline__ void split2(float a, float b, uint32_t& hp, uint32_t& lp) {
    __nv_bfloat16 ah = __float2bfloat16(a), bh = __float2bfloat16(b);
    float ar = a - __bfloat162float(ah), br = b - __bfloat162float(bh);
    __nv_bfloat16 al = __float2bfloat16(ar), bl = __float2bfloat16(br);
    hp = (uint32_t)__bfloat16_as_ushort(ah) | ((uint32_t)__bfloat16_as_ushort(bh) << 16);
    lp = (uint32_t)__bfloat16_as_ushort(al) | ((uint32_t)__bfloat16_as_ushort(bl) << 16);
}

// ---------------------------------------------------------------------------
// mma.sync / ldmatrix / cp.async primitives (arch-generic, sm_80+)
// ---------------------------------------------------------------------------
__device__ __forceinline__ uint32_t smem_u32(const void* p) {
    return (uint32_t)__cvta_generic_to_shared(p);
}

__device__ __forceinline__ void ldmA(uint32_t* r, uint32_t addr) {
    asm volatile("ldmatrix.sync.aligned.m8n8.x4.shared.b16 {%0,%1,%2,%3}, [%4];"
                 : "=r"(r[0]), "=r"(r[1]), "=r"(r[2]), "=r"(r[3]) : "r"(addr));
}

__device__ __forceinline__ void ldmT(uint32_t& r0, uint32_t& r1, uint32_t& r2, uint32_t& r3,
                                     uint32_t addr) {
    asm volatile("ldmatrix.sync.aligned.m8n8.x4.trans.shared.b16 {%0,%1,%2,%3}, [%4];"
                 : "=r"(r0), "=r"(r1), "=r"(r2), "=r"(r3) : "r"(addr));
}

__device__ __forceinline__ void mma16816(float* c, const uint32_t* a, const uint32_t* b) {
    asm volatile("mma.sync.aligned.m16n8k16.row.col.f32.bf16.bf16.f32 "
                 "{%0,%1,%2,%3}, {%4,%5,%6,%7}, {%8,%9}, {%0,%1,%2,%3};"
                 : "+f"(c[0]), "+f"(c[1]), "+f"(c[2]), "+f"(c[3])
                 : "r"(a[0]), "r"(a[1]), "r"(a[2]), "r"(a[3]), "r"(b[0]), "r"(b[1]));
}

__device__ __forceinline__ void cpa16(uint32_t s, const void* g) {
    asm volatile("cp.async.cg.shared.global [%0], [%1], 16;" :: "r"(s), "l"(g));
}
__device__ __forceinline__ void cpa_commit() { asm volatile("cp.async.commit_group;"); }
__device__ __forceinline__ void cpa_wait1()  { asm volatile("cp.async.wait_group 1;"); }

// ---------------------------------------------------------------------------
// Pipelined tensor-core GEMM: C[M,N] (op)= A[M,K] * B[K,N]
//   A, B both pre-split bf16 hi/lo. 3-term: AhBh + AlBh + AhBl.
//   CTA tile (MTILES*32) x 128 x 32, 8 warps (2m x 4n), 3-stage cp.async.
//   EPI 0: Cf = acc (split-K slice via blockIdx.z)
//   EPI 1: (Ch,Cl) = split(silu(acc))                 [no fp32 write]
//   EPI 2: Cf += acc; (Ch,Cl) = split(Cf)             [residual + next-A]
// ---------------------------------------------------------------------------
#define A_LD 40
#define B_LD 136

template<int MTILES, int EPI>
__global__ void __launch_bounds__(256)
gemm_mma(const __nv_bfloat16* __restrict__ Ah, const __nv_bfloat16* __restrict__ Al,
         const __nv_bfloat16* __restrict__ Bh, const __nv_bfloat16* __restrict__ Bl,
         float* __restrict__ Cf, __nv_bfloat16* __restrict__ Ch, __nv_bfloat16* __restrict__ Cl,
         int lda, int ldb, int ldc, int kchunk, int cslice)
{
    constexpr int BM = MTILES * 32;
    constexpr int A_E = BM * A_LD;            // elems per A buffer
    constexpr int B_E = 32 * B_LD;            // 4352
    constexpr int STAGE_B = (2 * A_E + 2 * B_E) * 2;  // bytes per stage
    constexpr int OFS_AL = A_E * 2;
    constexpr int OFS_BH = 2 * A_E * 2;
    constexpr int OFS_BL = 2 * A_E * 2 + B_E * 2;

    extern __shared__ __align__(16) char smem[];
    const uint32_t sb = smem_u32(smem);

    const int tid  = threadIdx.x;
    const int lane = tid & 31;
    const int wid  = tid >> 5;
    const int wm = (wid & 1) * (MTILES * 16);
    const int wn = (wid >> 1) * 32;
    const int mbase = blockIdx.y * BM;
    const int nbase = blockIdx.x * 128;
    const int kbeg  = blockIdx.z * kchunk;
    const int niter = kchunk >> 5;

    float acc[MTILES][4][4];
#pragma unroll
    for (int i = 0; i < MTILES; i++)
#pragma unroll
        for (int j = 0; j < 4; j++)
#pragma unroll
            for (int f = 0; f < 4; f++) acc[i][j][f] = 0.f;

    // cp.async issue for one stage
    auto issue = [&](int st, int k0) {
        const uint32_t s0 = sb + st * STAGE_B;
#pragma unroll
        for (int i = 0; i < BM / 64; i++) {
            const int q = tid + i * 256;            // A chunk id
            const int row = q >> 2, c16 = q & 3;
            const size_t ga = (size_t)(mbase + row) * lda + k0 + c16 * 8;
            const uint32_t so = (uint32_t)(row * A_LD + c16 * 8) * 2;
            cpa16(s0 + so, Ah + ga);
            cpa16(s0 + OFS_AL + so, Al + ga);
        }
#pragma unroll
        for (int i = 0; i < 2; i++) {
            const int q = tid + i * 256;            // B chunk id
            const int kr = q >> 4, c16 = q & 15;
            const size_t gb = (size_t)(k0 + kr) * ldb + nbase + c16 * 8;
            const uint32_t so = (uint32_t)(kr * B_LD + c16 * 8) * 2;
            cpa16(s0 + OFS_BH + so, Bh + gb);
            cpa16(s0 + OFS_BL + so, Bl + gb);
        }
    };

    issue(0, kbeg);          cpa_commit();
    issue(1, kbeg + 32);     cpa_commit();

    for (int c = 0; c < niter; ++c) {
        cpa_wait1();
        __syncthreads();
        if (c + 2 < niter) issue((c + 2) % 3, kbeg + (c + 2) * 32);
        cpa_commit();

        const uint32_t s0 = sb + (c % 3) * STAGE_B;
#pragma unroll
        for (int ks = 0; ks < 32; ks += 16) {
            uint32_t Af[MTILES][4], Alf[MTILES][4];
#pragma unroll
            for (int mt = 0; mt < MTILES; mt++) {
                const uint32_t off = (uint32_t)((wm + mt * 16 + (lane & 15)) * A_LD
                                                + ks + (lane >> 4) * 8) * 2;
                ldmA(Af[mt],  s0 + off);
                ldmA(Alf[mt], s0 + OFS_AL + off);
            }
            uint32_t Bf[4][2], Blf[4][2];
#pragma unroll
            for (int g = 0; g < 2; g++) {
                const uint32_t off = (uint32_t)((ks + (lane & 15)) * B_LD
                                                + wn + g * 16 + (lane >> 4) * 8) * 2;
                ldmT(Bf[2*g][0], Bf[2*g][1], Bf[2*g+1][0], Bf[2*g+1][1], s0 + OFS_BH + off);
                ldmT(Blf[2*g][0], Blf[2*g][1], Blf[2*g+1][0], Blf[2*g+1][1], s0 + OFS_BL + off);
            }
#pragma unroll
            for (int mt = 0; mt < MTILES; mt++)
#pragma unroll
                for (int nt = 0; nt < 4; nt++) {
                    mma16816(acc[mt][nt], Af[mt],  Bf[nt]);
                    mma16816(acc[mt][nt], Alf[mt], Bf[nt]);
                    mma16816(acc[mt][nt], Af[mt],  Blf[nt]);
                }
        }
    }

    // epilogue
    float* Cb = (EPI == 0) ? (Cf + (size_t)blockIdx.z * cslice) : Cf;
    const int tr = lane >> 2, tc = (lane & 3) * 2;
#pragma unroll
    for (int mt = 0; mt < MTILES; mt++) {
#pragma unroll
        for (int nt = 0; nt < 4; nt++) {
#pragma unroll
            for (int half = 0; half < 2; half++) {
                const int row = mbase + wm + mt * 16 + tr + half * 8;
                const int col = nbase + wn + nt * 8 + tc;
                float2 v = make_float2(acc[mt][nt][half * 2], acc[mt][nt][half * 2 + 1]);
                if (EPI == 0) {
                    *(float2*)(Cb + (size_t)row * ldc + col) = v;
                } else if (EPI == 1) {
                    v.x = silu_f(v.x); v.y = silu_f(v.y);
                    uint32_t hp, lp;
                    split2(v.x, v.y, hp, lp);
                    *(uint32_t*)(Ch + (size_t)row * ldc + col) = hp;
                    *(uint32_t*)(Cl + (size_t)row * ldc + col) = lp;
                } else {
                    float* p = Cb + (size_t)row * ldc + col;
                    float2 o = *(float2*)p;
                    v.x += o.x; v.y += o.y;
                    *(float2*)p = v;
                    uint32_t hp, lp;
                    split2(v.x, v.y, hp, lp);
                    *(uint32_t*)(Ch + (size_t)row * ldc + col) = hp;
                    *(uint32_t*)(Cl + (size_t)row * ldc + col) = lp;
                }
            }
        }
    }
}

// ---------------------------------------------------------------------------
// fp32 -> bf16 hi/lo split (elementwise)
// ---------------------------------------------------------------------------
__global__ void split_k(const float* __restrict__ src,
                        __nv_bfloat16* __restrict__ hi, __nv_bfloat16* __restrict__ lo, int n4)
{
    const int i = blockIdx.x * blockDim.x + threadIdx.x;
    if (i >= n4) return;
    const float4 v = ((const float4*)src)[i];
    uint32_t h0, l0, h1, l1;
    split2(v.x, v.y, h0, l0);
    split2(v.z, v.w, h1, l1);
    ((uint2*)hi)[i] = make_uint2(h0, h1);
    ((uint2*)lo)[i] = make_uint2(l0, l1);
}

// ---------------------------------------------------------------------------
// Small kernels
// ---------------------------------------------------------------------------
__global__ void compute_starts_k(const int* __restrict__ seg, int* __restrict__ starts,
                                 int* __restrict__ ends)
{
    int b = threadIdx.x;
    if (b >= Bsz) return;
    int cnt = 0;
    for (int t = 0; t < Lseq && cnt < NSEG; t++)
        if (seg[b * Lseq + t] != 0) starts[b * NSEG + cnt++] = t;
    while (cnt < NSEG) { starts[b * NSEG + cnt] = 0; cnt++; }
    for (int i = 0; i < NSEG - 1; i++) ends[b * NSEG + i] = starts[b * NSEG + i + 1];
    ends[b * NSEG + NSEG - 1] = Lseq;
}

// x = E[id]; also write bf16 hi/lo
__global__ void gather_correct_k(const int* __restrict__ ids, const float* __restrict__ E,
                                 float* __restrict__ x,
                                 __nv_bfloat16* __restrict__ xh, __nv_bfloat16* __restrict__ xl)
{
    const int row = blockIdx.x;
    const int id = ids[row];
    const float4 v = ((const float4*)(E + (size_t)id * Dm))[threadIdx.x];
    ((float4*)(x + (size_t)row * Dm))[threadIdx.x] = v;
    uint32_t h0, l0, h1, l1;
    split2(v.x, v.y, h0, l0);
    split2(v.z, v.w, h1, l1);
    ((uint2*)(xh + (size_t)row * Dm))[threadIdx.x] = make_uint2(h0, h1);
    ((uint2*)(xl + (size_t)row * Dm))[threadIdx.x] = make_uint2(l0, l1);
}

// Fused recurrence + gate: h_t = a*h_{t-1} + u_t ; p_t = silu(g_t)*h_t -> bf16 hi/lo
__global__ void recurrence_k(const float* __restrict__ ug, const float* __restrict__ Avec,
                             float* __restrict__ hout,
                             __nv_bfloat16* __restrict__ ph, __nv_bfloat16* __restrict__ pl,
                             const float* __restrict__ init, int seqlen)
{
    const int idx = blockIdx.x * blockDim.x + threadIdx.x;
    const int q = idx >> 10;
    const int c = idx & (INNER - 1);
    const float a = Avec[c];
    const float* up = ug + (size_t)q * seqlen * (2 * INNER) + c;
    const float* gp = up + INNER;
    float hv = init ? init[idx] : 0.f;
    for (int t = 0; t < seqlen; t++) {
        hv = fmaf(a, hv, up[(size_t)t * (2 * INNER)]);
        if (hout) hout[((size_t)q * seqlen + t) * INNER + c] = hv;
        const float g = gp[(size_t)t * (2 * INNER)];
        const float p = silu_f(g) * hv;
        const __nv_bfloat16 hi = __float2bfloat16(p);
        const __nv_bfloat16 lo = __float2bfloat16(p - __bfloat162float(hi));
        ph[((size_t)q * seqlen + t) * INNER + c] = hi;
        pl[((size_t)q * seqlen + t) * INNER + c] = lo;
    }
}

__global__ void save_state_k(const float* __restrict__ h, float* __restrict__ st,
                             const int* __restrict__ starts)
{
    const int r = blockIdx.x;
    const int c = threadIdx.x;
    const int b = r >> 3;
    const int s = starts[r];
    st[(size_t)r * INNER + c] = (s > 0) ? h[((size_t)b * Lseq + (s - 1)) * INNER + c] : 0.f;
}

// xs[q,t,:] = sum_sk decpart[sk][b, s_q + t, :]  (zero past end); also bf16 hi/lo
__global__ void build_xs_k(const float* __restrict__ part, float* __restrict__ xs,
                           __nv_bfloat16* __restrict__ xsh, __nv_bfloat16* __restrict__ xsl,
                           const int* __restrict__ starts, const int* __restrict__ ends)
{
    const int r = blockIdx.x;
    const int q = r >> 7;
    const int t = r & (SEGLEN - 1);
    const int b = q >> 3;
    const int s = starts[q], e = ends[q];
    const int pos = s + t;
    float4 v = make_float4(0.f, 0.f, 0.f, 0.f);
    if (pos < e && pos < Lseq) {
        const size_t base = ((size_t)b * Lseq + pos) * Dm;
#pragma unroll
        for (int p = 0; p < DEC_SK; p++) {
            const float4 w = ((const float4*)(part + (size_t)p * NROWS * Dm + base))[threadIdx.x];
            v.x += w.x; v.y += w.y; v.z += w.z; v.w += w.w;
        }
    }
    ((float4*)(xs + (size_t)r * Dm))[threadIdx.x] = v;
    uint32_t h0, l0, h1, l1;
    split2(v.x, v.y, h0, l0);
    split2(v.z, v.w, h1, l1);
    ((uint2*)(xsh + (size_t)r * Dm))[threadIdx.x] = make_uint2(h0, h1);
    ((uint2*)(xsl + (size_t)r * Dm))[threadIdx.x] = make_uint2(l0, l1);
}

__global__ void extract_last_k(const float* __restrict__ xs, float* __restrict__ last,
                               const int* __restrict__ starts, const int* __restrict__ ends)
{
    const int q = blockIdx.x;
    int len = ends[q] - starts[q];
    if (len > SEGLEN) len = SEGLEN;
    if (len < 1) len = 1;
    const float4* s = (const float4*)(xs + ((size_t)q * SEGLEN + (len - 1)) * Dm);
    float4* d = (float4*)(last + (size_t)q * Dm);
    d[threadIdx.x] = s[threadIdx.x];
}

__global__ void head_k(const float* __restrict__ last,
                       const float* __restrict__ muW, const float* __restrict__ mub,
                       const float* __restrict__ lvW, const float* __restrict__ lvb,
                       float* __restrict__ out)
{
    const int o = blockIdx.x * blockDim.x + threadIdx.x;
    const int which = o >> 13;
    const int rem = o & 8191;
    const int r = rem >> 9, d = rem & 511;
    const float* W = which ? lvW : muW;
    const float* bias = which ? lvb : mub;
    const float* lr = last + (size_t)r * Dm;
    float acc = bias[d];
#pragma unroll 8
    for (int k = 0; k < Dm; k++) acc = fmaf(lr[k], W[(size_t)k * Dm + d], acc);
    out[o] = acc;
}

// ---------------------------------------------------------------------------
// Orchestration
// ---------------------------------------------------------------------------
extern "C" void kernel_launch(void* const* d_in, const int* in_sizes, int n_in,
                              void* d_out, int out_size)
{
    const float* decoder_output = (const float*)d_in[0];
    const int*   input_ids      = (const int*)  d_in[1];
    const int*   seg_idx        = (const int*)  d_in[2];
    const float* E              = (const float*)d_in[3];
    const float* Aparam         = (const float*)d_in[4];
    const float* Win            = (const float*)d_in[5];
    const float* Wout           = (const float*)d_in[6];
    const float* Wm1            = (const float*)d_in[7];
    const float* Wm2            = (const float*)d_in[8];
    const float* muW            = (const float*)d_in[9];
    const float* mub            = (const float*)d_in[10];
    const float* lvW            = (const float*)d_in[11];
    const float* lvb            = (const float*)d_in[12];
    float* out = (float*)d_out;

    float *x, *decpart, *ug, *h, *xs, *state, *last;
    int *starts, *ends;
    __nv_bfloat16 *decAh, *decAl, *xh, *xl, *ph, *pl, *mlph, *mlpl;
    __nv_bfloat16 *eh, *el, *winh, *winl, *wouth, *woutl, *wm1h, *wm1l, *wm2h, *wm2l;
    cudaGetSymbolAddress((void**)&x,       g_x);
    cudaGetSymbolAddress((void**)&decpart, g_decpart);
    cudaGetSymbolAddress((void**)&ug,      g_ug);
    cudaGetSymbolAddress((void**)&h,       g_h);
    cudaGetSymbolAddress((void**)&xs,      g_xs);
    cudaGetSymbolAddress((void**)&state,   g_state);
    cudaGetSymbolAddress((void**)&last,    g_last);
    cudaGetSymbolAddress((void**)&starts,  g_starts);
    cudaGetSymbolAddress((void**)&ends,    g_ends);
    cudaGetSymbolAddress((void**)&decAh,   g_decAh);
    cudaGetSymbolAddress((void**)&decAl,   g_decAl);
    cudaGetSymbolAddress((void**)&xh,      g_xh);
    cudaGetSymbolAddress((void**)&xl,      g_xl);
    cudaGetSymbolAddress((void**)&ph,      g_ph);
    cudaGetSymbolAddress((void**)&pl,      g_pl);
    cudaGetSymbolAddress((void**)&mlph,    g_mlph);
    cudaGetSymbolAddress((void**)&mlpl,    g_mlpl);
    cudaGetSymbolAddress((void**)&eh,      g_Eh);
    cudaGetSymbolAddress((void**)&el,      g_El);
    cudaGetSymbolAddress((void**)&winh,    g_WinH);
    cudaGetSymbolAddress((void**)&winl,    g_WinL);
    cudaGetSymbolAddress((void**)&wouth,   g_WoutH);
    cudaGetSymbolAddress((void**)&woutl,   g_WoutL);
    cudaGetSymbolAddress((void**)&wm1h,    g_Wm1H);
    cudaGetSymbolAddress((void**)&wm1l,    g_Wm1L);
    cudaGetSymbolAddress((void**)&wm2h,    g_Wm2H);
    cudaGetSymbolAddress((void**)&wm2l,    g_Wm2L);

    // dynamic smem opt-in for the 3 GEMM instantiations
    constexpr int SM40 = (2 * 128 * A_LD + 2 * 32 * B_LD) * 2 * 3;  // MTILES=4
    constexpr int SM20 = (2 * 64  * A_LD + 2 * 32 * B_LD) * 2 * 3;  // MTILES=2
    cudaFuncSetAttribute(gemm_mma<4, 0>, cudaFuncAttributeMaxDynamicSharedMemorySize, SM40);
    cudaFuncSetAttribute(gemm_mma<4, 1>, cudaFuncAttributeMaxDynamicSharedMemorySize, SM40);
    cudaFuncSetAttribute(gemm_mma<2, 2>, cudaFuncAttributeMaxDynamicSharedMemorySize, SM20);

    // Pre-split all static B operands + decoder A
    auto split = [&](const float* s, __nv_bfloat16* hh, __nv_bfloat16* ll, size_t n) {
        split_k<<<(int)((n / 4 + 255) / 256), 256>>>(s, hh, ll, (int)(n / 4));
    };
    split(E,    eh,    el,    (size_t)VOC * Dm);
    split(Win,  winh,  winl,  (size_t)NLAY * Dm * 2 * INNER);
    split(Wout, wouth, woutl, (size_t)NLAY * INNER * Dm);
    split(Wm1,  wm1h,  wm1l,  (size_t)NLAY * Dm * MLPD);
    split(Wm2,  wm2h,  wm2l,  (size_t)NLAY * MLPD * Dm);
    split(decoder_output, decAh, decAl, (size_t)NROWS * VOC);

    compute_starts_k<<<1, 32>>>(seg_idx, starts, ends);
    gather_correct_k<<<NROWS, 128>>>(input_ids, E, x, xh, xl);

    // dec = decoder_output @ E  (split-K=8 over 32000)
    gemm_mma<4, 0><<<dim3(Dm / 128, NROWS / 128, DEC_SK), 256, SM40>>>(
        decAh, decAl, eh, el, decpart, nullptr, nullptr,
        VOC, Dm, Dm, DEC_KSLICE, NROWS * Dm);

    // -------- Base pass --------
    for (int l = 0; l < NLAY; l++) {
        const size_t oWin  = (size_t)l * Dm * 2 * INNER;
        const size_t oWout = (size_t)l * INNER * Dm;
        const size_t oWm1  = (size_t)l * Dm * MLPD;
        const size_t oWm2  = (size_t)l * MLPD * Dm;
        const float* Al    = Aparam + (size_t)l * INNER;
        float* stl = state + (size_t)l * Bsz * NSEG * INNER;

        gemm_mma<4, 0><<<dim3((2 * INNER) / 128, NROWS / 128, 1), 256, SM40>>>(
            xh, xl, winh + oWin, winl + oWin, ug, nullptr, nullptr,
            Dm, 2 * INNER, 2 * INNER, Dm, 0);
        recurrence_k<<<(Bsz * INNER) / 256, 256>>>(ug, Al, h, ph, pl, nullptr, Lseq);
        save_state_k<<<Bsz * NSEG, INNER>>>(h, stl, starts);
        gemm_mma<2, 2><<<dim3(Dm / 128, NROWS / 64, 1), 256, SM20>>>(
            ph, pl, wouth + oWout, woutl + oWout, x, xh, xl,
            INNER, Dm, Dm, INNER, 0);
        gemm_mma<4, 1><<<dim3(MLPD / 128, NROWS / 128, 1), 256, SM40>>>(
            xh, xl, wm1h + oWm1, wm1l + oWm1, nullptr, mlph, mlpl,
            Dm, MLPD, MLPD, Dm, 0);
        gemm_mma<2, 2><<<dim3(Dm / 128, NROWS / 64, 1), 256, SM20>>>(
            mlph, mlpl, wm2h + oWm2, wm2l + oWm2, x, xh, xl,
            MLPD, Dm, Dm, MLPD, 0);
    }

    // -------- Segment pass --------
    build_xs_k<<<NROWS, 128>>>(decpart, xs, xh, xl, starts, ends);
    for (int l = 0; l < NLAY; l++) {
        const size_t oWin  = (size_t)l * Dm * 2 * INNER;
        const size_t oWout = (size_t)l * INNER * Dm;
        const size_t oWm1  = (size_t)l * Dm * MLPD;
        const size_t oWm2  = (size_t)l * MLPD * Dm;
        const float* Al    = Aparam + (size_t)l * INNER;
        const float* stl = state + (size_t)l * Bsz * NSEG * INNER;

        gemm_mma<4, 0><<<dim3((2 * INNER) / 128, NROWS / 128, 1), 256, SM40>>>(
            xh, xl, winh + oWin, winl + oWin, ug, nullptr, nullptr,
            Dm, 2 * INNER, 2 * INNER, Dm, 0);
        recurrence_k<<<(Bsz * NSEG * INNER) / 256, 256>>>(ug, Al, nullptr, ph, pl, stl, SEGLEN);
        gemm_mma<2, 2><<<dim3(Dm / 128, NROWS / 64, 1), 256, SM20>>>(
            ph, pl, wouth + oWout, woutl + oWout, xs, xh, xl,
            INNER, Dm, Dm, INNER, 0);
        gemm_mma<4, 1><<<dim3(MLPD / 128, NROWS / 128, 1), 256, SM40>>>(
            xh, xl, wm1h + oWm1, wm1l + oWm1, nullptr, mlph, mlpl,
            Dm, MLPD, MLPD, Dm, 0);
        gemm_mma<2, 2><<<dim3(Dm / 128, NROWS / 64, 1), 256, SM20>>>(
            mlph, mlpl, wm2h + oWm2, wm2l + oWm2, xs, xh, xl,
            MLPD, Dm, Dm, MLPD, 0);
    }

    extract_last_k<<<Bsz * NSEG, 128>>>(xs, last, starts, ends);
    head_k<<<(2 * Bsz * NSEG * Dm) / 256, 256>>>(last, muW, mub, lvW, lvb, out);
}